// round 6
// baseline (speedup 1.0000x reference)
#include <cuda_runtime.h>
#include <cuda_fp16.h>

// ResLSTM on GB300, round 6:
//  - batch-pair f32x2 packing: accumulator holds (gate g, batches b0|b1);
//    operands naturally packed in smem (no per-iter pk2), weights duplicated
//    once per load and reused (Phase A: 10x, Phase B: 2x).
//  - fp16 weights: Phase B recurrent in smem as __half (LDS.64, half the
//    crossbar bytes of the dominant traffic term); Phase A input weights
//    streamed as __half from prep-transposed __device__ arrays (LDG.64).
//  - warp = 4 batches (2 batch-pairs), lane = hidden unit j; 128-thr CTAs,
//    3 CTAs/SM.

#define NT      128
#define NWARP   4
#define NB      4
#define B_TOTAL 131072
#define TT      5
#define NF      62

typedef unsigned long long ull;

// pre-transposed fp16 input weights: [row][j*4+g]
__device__ __align__(16) __half g_WI0H[64 * 128];   // rows 62,63 zero-padded
__device__ __align__(16) __half g_WI1H[32 * 128];

// ---- shared layout (floats) ----
#define OFF_WH0H 0                      // 32*128 halves = 2048 floats
#define OFF_W1RH (OFF_WH0H + 2048)      // 2048 floats
#define OFF_B0   (OFF_W1RH + 2048)      // 128 (interleaved j*4+g)
#define OFF_B1   (OFF_B0 + 128)
#define OFF_G0   (OFF_B1 + 128)
#define OFF_BE0  (OFF_G0 + 160)
#define OFF_G1   (OFF_BE0 + 160)
#define OFF_BE1  (OFF_G1 + 160)
#define OFF_DW   (OFF_BE1 + 160)        // 480
#define OFF_DB   (OFF_DW + 480)         // 4
#define OFF_SCR  (OFF_DB + 4)
// per-warp scratch (floats):
//   X  [t][bp][n][2]  : 5*2*64*2 = 1280
//   H  [bp][k][2]     : 2*32*2   = 128
//   O0 [t][bp][j][2]  : 5*2*32*2 = 640
#define SCR_W   2048
#define SMEM_FLOATS (OFF_SCR + NWARP * SCR_W)
#define SMEM_BYTES  (SMEM_FLOATS * 4)

__device__ __forceinline__ float tanh_f(float x) {
    float y; asm("tanh.approx.f32 %0, %1;" : "=f"(y) : "f"(x)); return y;
}
__device__ __forceinline__ float sigm(float x) {
    return fmaf(0.5f, tanh_f(0.5f * x), 0.5f);
}
__device__ __forceinline__ float lrelu(float x) {
    return x > 0.0f ? x : 0.01f * x;
}
__device__ __forceinline__ ull pk2(float x) {
    ull r; asm("mov.b64 %0, {%1, %2};" : "=l"(r) : "f"(x), "f"(x)); return r;
}
__device__ __forceinline__ void fma2(ull& d, ull a, ull b) {
    asm("fma.rn.f32x2 %0, %1, %2, %0;" : "+l"(d) : "l"(a), "l"(b));
}
__device__ __forceinline__ void unpk(ull v, float& lo, float& hi) {
    asm("mov.b64 {%0, %1}, %2;" : "=f"(lo), "=f"(hi) : "l"(v));
}
// half2 word -> two duplicated f32x2 pairs (w0,w0), (w1,w1)
__device__ __forceinline__ void h2dup(unsigned int h2, ull& d0, ull& d1) {
    asm("{\n\t"
        ".reg .f16 a, b;\n\t"
        ".reg .f32 f, g;\n\t"
        "mov.b32 {a, b}, %2;\n\t"
        "cvt.f32.f16 f, a;\n\t"
        "cvt.f32.f16 g, b;\n\t"
        "mov.b64 %0, {f, f};\n\t"
        "mov.b64 %1, {g, g};\n\t"
        "}"
        : "=l"(d0), "=l"(d1) : "r"(h2));
}

// ---------------- prep: transpose input weights to fp16 [row][j*4+g] -------
__global__ void prep_kernel(const float* __restrict__ w_ih0,
                            const float* __restrict__ w_ih1) {
    for (int i = blockIdx.x * blockDim.x + threadIdx.x; i < 64 * 128;
         i += blockDim.x * gridDim.x) {
        int n = i >> 7, rem = i & 127, j = rem >> 2, g = rem & 3;
        g_WI0H[i] = __float2half((n < NF) ? w_ih0[(g * 32 + j) * NF + n] : 0.0f);
        if (n < 32) g_WI1H[i] = __float2half(w_ih1[(g * 32 + j) * 32 + n]);
    }
}

// input phase: stream NG 4-row weight groups once (fp16), reuse duplicated
// f32x2 weight regs across 5 timesteps x 2 batch-pairs.
__device__ __forceinline__ void phaseA(
    const __half* __restrict__ Wh, const float* __restrict__ vec,
    int tstride, int bstride, int nG, int lane, ull acc[TT][2][4])
{
#pragma unroll 1
    for (int g = 0; g < nG; g++) {
        ull wd[4][4];
#pragma unroll
        for (int r = 0; r < 4; r++) {
            uint2 hw = *(const uint2*)(Wh + ((4 * g + r) * 128 + lane * 4));
            h2dup(hw.x, wd[r][0], wd[r][1]);
            h2dup(hw.y, wd[r][2], wd[r][3]);
        }
#pragma unroll
        for (int t = 0; t < TT; t++) {
#pragma unroll
            for (int bp = 0; bp < 2; bp++) {
                const float* vp = vec + t * tstride + bp * bstride + g * 8;
                ulonglong2 xa = *(const ulonglong2*)(vp);       // rows r=0,1
                ulonglong2 xb = *(const ulonglong2*)(vp + 4);   // rows r=2,3
                fma2(acc[t][bp][0], xa.x, wd[0][0]);
                fma2(acc[t][bp][1], xa.x, wd[0][1]);
                fma2(acc[t][bp][2], xa.x, wd[0][2]);
                fma2(acc[t][bp][3], xa.x, wd[0][3]);
                fma2(acc[t][bp][0], xa.y, wd[1][0]);
                fma2(acc[t][bp][1], xa.y, wd[1][1]);
                fma2(acc[t][bp][2], xa.y, wd[1][2]);
                fma2(acc[t][bp][3], xa.y, wd[1][3]);
                fma2(acc[t][bp][0], xb.x, wd[2][0]);
                fma2(acc[t][bp][1], xb.x, wd[2][1]);
                fma2(acc[t][bp][2], xb.x, wd[2][2]);
                fma2(acc[t][bp][3], xb.x, wd[2][3]);
                fma2(acc[t][bp][0], xb.y, wd[3][0]);
                fma2(acc[t][bp][1], xb.y, wd[3][1]);
                fma2(acc[t][bp][2], xb.y, wd[3][2]);
                fma2(acc[t][bp][3], xb.y, wd[3][3]);
            }
        }
    }
}

// recurrent phase: one 4-row group, fp16 weights from smem, h packed by bp
__device__ __forceinline__ void phaseB_g(
    const __half* __restrict__ Wh, const float* __restrict__ hvec,
    int g, int lane, ull acc[2][4])
{
    ull wd[4][4];
#pragma unroll
    for (int r = 0; r < 4; r++) {
        uint2 hw = *(const uint2*)(Wh + ((4 * g + r) * 128 + lane * 4));
        h2dup(hw.x, wd[r][0], wd[r][1]);
        h2dup(hw.y, wd[r][2], wd[r][3]);
    }
#pragma unroll
    for (int bp = 0; bp < 2; bp++) {
        const float* hp = hvec + bp * 64 + g * 8;
        ulonglong2 ha = *(const ulonglong2*)(hp);
        ulonglong2 hb = *(const ulonglong2*)(hp + 4);
        fma2(acc[bp][0], ha.x, wd[0][0]);
        fma2(acc[bp][1], ha.x, wd[0][1]);
        fma2(acc[bp][2], ha.x, wd[0][2]);
        fma2(acc[bp][3], ha.x, wd[0][3]);
        fma2(acc[bp][0], ha.y, wd[1][0]);
        fma2(acc[bp][1], ha.y, wd[1][1]);
        fma2(acc[bp][2], ha.y, wd[1][2]);
        fma2(acc[bp][3], ha.y, wd[1][3]);
        fma2(acc[bp][0], hb.x, wd[2][0]);
        fma2(acc[bp][1], hb.x, wd[2][1]);
        fma2(acc[bp][2], hb.x, wd[2][2]);
        fma2(acc[bp][3], hb.x, wd[2][3]);
        fma2(acc[bp][0], hb.y, wd[3][0]);
        fma2(acc[bp][1], hb.y, wd[3][1]);
        fma2(acc[bp][2], hb.y, wd[3][2]);
        fma2(acc[bp][3], hb.y, wd[3][3]);
    }
}

__global__ __launch_bounds__(NT, 3) void reslstm_kernel(
    const float* __restrict__ data,
    const float* __restrict__ w_hh0,
    const float* __restrict__ b_ih0, const float* __restrict__ b_hh0,
    const float* __restrict__ g0,    const float* __restrict__ be0,
    const float* __restrict__ w_hh1,
    const float* __restrict__ b_ih1, const float* __restrict__ b_hh1,
    const float* __restrict__ g1,    const float* __restrict__ be1,
    const float* __restrict__ dw,    const float* __restrict__ db,
    float* __restrict__ out)
{
    extern __shared__ float sm[];
    __half* sWH0h = (__half*)(sm + OFF_WH0H);
    __half* sW1Rh = (__half*)(sm + OFF_W1RH);
    float* sB0  = sm + OFF_B0;
    float* sB1  = sm + OFF_B1;
    float* sG0  = sm + OFF_G0;
    float* sBe0 = sm + OFF_BE0;
    float* sG1  = sm + OFF_G1;
    float* sBe1 = sm + OFF_BE1;
    float* sDW  = sm + OFF_DW;
    float* sDB  = sm + OFF_DB;

    const int tid  = threadIdx.x;
    const int lane = tid & 31;
    const int wid  = tid >> 5;

    // stage recurrent weights as fp16, transposed+interleaved [k][j*4+g]
    for (int i = tid; i < 32 * 128; i += NT) {
        int k = i >> 7, rem = i & 127, j = rem >> 2, g = rem & 3;
        sWH0h[i] = __float2half(w_hh0[(g * 32 + j) * 32 + k]);
        sW1Rh[i] = __float2half(w_hh1[(g * 32 + j) * 32 + k]);
    }
    for (int i = tid; i < 128; i += NT) {
        int j = i >> 2, g = i & 3;
        sB0[i] = b_ih0[g * 32 + j] + b_hh0[g * 32 + j];
        sB1[i] = b_ih1[g * 32 + j] + b_hh1[g * 32 + j];
    }
    for (int i = tid; i < 160; i += NT) {
        sG0[i] = g0[i]; sBe0[i] = be0[i];
        sG1[i] = g1[i]; sBe1[i] = be1[i];
    }
    for (int i = tid; i < 480; i += NT) sDW[i] = dw[i];
    if (tid < 3) sDB[tid] = db[tid];

    float* scrX  = sm + OFF_SCR + wid * SCR_W;  // [t*256 + bp*128 + n*2 + b]
    float* scrH  = scrX + 1280;                 // [bp*64 + k*2 + b]
    float* scrO0 = scrH + 128;                  // [t*128 + bp*64 + j*2 + b]

    const long long base = ((long long)blockIdx.x * NWARP + wid) * NB;

    // stage X (pad n=62,63 with 0); init h = 0
#pragma unroll
    for (int bi = 0; bi < NB; bi++) {
        int bp = bi >> 1, b = bi & 1;
        const float* dp = data + (base + bi) * (NF * TT);
        float* xw = scrX + bp * 128 + b;
#pragma unroll
        for (int t = 0; t < TT; t++) {
            xw[t * 256 + lane * 2] = __ldg(dp + lane * TT + t);
            float xv = (lane < NF - 32) ? __ldg(dp + (lane + 32) * TT + t) : 0.0f;
            xw[t * 256 + (lane + 32) * 2] = xv;
        }
    }
    scrH[lane] = 0.0f;
    scrH[64 + lane] = 0.0f;
    scrH[32 + lane] = 0.0f;
    scrH[96 + lane] = 0.0f;
    __syncthreads();

    const unsigned FULL = 0xffffffffu;

    // duplicated biases (per lane: 4 gate scalars)
    float4 b0q = *(const float4*)(sB0 + lane * 4);
    ull b0d[4] = { pk2(b0q.x), pk2(b0q.y), pk2(b0q.z), pk2(b0q.w) };

    // ======== layer 0: input phase (hoisted over t) ========
    ull acc[TT][2][4];
#pragma unroll
    for (int t = 0; t < TT; t++)
#pragma unroll
        for (int bp = 0; bp < 2; bp++)
#pragma unroll
            for (int g = 0; g < 4; g++) acc[t][bp][g] = b0d[g];

    phaseA(g_WI0H, scrX, 256, 128, 16, lane, acc);

    // ======== layer 0: recurrent phase ========
    float c0[NB];
#pragma unroll
    for (int bi = 0; bi < NB; bi++) c0[bi] = 0.f;

#pragma unroll
    for (int t = 0; t < TT; t++) {
#pragma unroll 1
        for (int g = 0; g < 8; g++)
            phaseB_g(sWH0h, scrH, g, lane, acc[t]);
#pragma unroll
        for (int bi = 0; bi < NB; bi++) {
            int bp = bi >> 1, b = bi & 1;
            float gi0, gi1, gf0, gf1, gg0, gg1, go0, go1;
            unpk(acc[t][bp][0], gi0, gi1);
            unpk(acc[t][bp][1], gf0, gf1);
            unpk(acc[t][bp][2], gg0, gg1);
            unpk(acc[t][bp][3], go0, go1);
            float ai = b ? gi1 : gi0;
            float af = b ? gf1 : gf0;
            float ag = b ? gg1 : gg0;
            float ao = b ? go1 : go0;
            float ig = sigm(ai), fg = sigm(af);
            float gg = tanh_f(ag), og = sigm(ao);
            c0[bi] = fg * c0[bi] + ig * gg;
            float h = og * tanh_f(c0[bi]);
            scrH[bp * 64 + lane * 2 + b] = h;
            scrO0[t * 128 + bp * 64 + lane * 2 + b] = h;
        }
        __syncwarp();
    }

    // ---- LN0 + LeakyReLU (in place in scrO0) ----
#pragma unroll
    for (int bi = 0; bi < NB; bi++) {
        int bp = bi >> 1, b = bi & 1;
        float v[TT];
        float s = 0.f, sq = 0.f;
#pragma unroll
        for (int t = 0; t < TT; t++) {
            v[t] = scrO0[t * 128 + bp * 64 + lane * 2 + b];
            s += v[t]; sq += v[t] * v[t];
        }
#pragma unroll
        for (int off = 16; off > 0; off >>= 1) {
            s  += __shfl_xor_sync(FULL, s,  off);
            sq += __shfl_xor_sync(FULL, sq, off);
        }
        float mu  = s * (1.0f / 160.0f);
        float var = sq * (1.0f / 160.0f) - mu * mu;
        float rs  = rsqrtf(var + 1e-5f);
#pragma unroll
        for (int t = 0; t < TT; t++) {
            float y = (v[t] - mu) * rs * sG0[t * 32 + lane] + sBe0[t * 32 + lane];
            scrO0[t * 128 + bp * 64 + lane * 2 + b] = lrelu(y);
        }
    }
    // reset h for layer 1
    scrH[lane] = 0.0f;
    scrH[64 + lane] = 0.0f;
    scrH[32 + lane] = 0.0f;
    scrH[96 + lane] = 0.0f;
    __syncwarp();

    // ======== layer 1: input phase over post-LN o0 ========
    float4 b1q = *(const float4*)(sB1 + lane * 4);
    ull b1d[4] = { pk2(b1q.x), pk2(b1q.y), pk2(b1q.z), pk2(b1q.w) };
#pragma unroll
    for (int t = 0; t < TT; t++)
#pragma unroll
        for (int bp = 0; bp < 2; bp++)
#pragma unroll
            for (int g = 0; g < 4; g++) acc[t][bp][g] = b1d[g];

    phaseA(g_WI1H, scrO0, 128, 64, 8, lane, acc);

    // ======== layer 1: recurrent phase ========
    float c1[NB];
    float o1[TT][NB];
#pragma unroll
    for (int bi = 0; bi < NB; bi++) c1[bi] = 0.f;

#pragma unroll
    for (int t = 0; t < TT; t++) {
#pragma unroll 1
        for (int g = 0; g < 8; g++)
            phaseB_g(sW1Rh, scrH, g, lane, acc[t]);
#pragma unroll
        for (int bi = 0; bi < NB; bi++) {
            int bp = bi >> 1, b = bi & 1;
            float gi0, gi1, gf0, gf1, gg0, gg1, go0, go1;
            unpk(acc[t][bp][0], gi0, gi1);
            unpk(acc[t][bp][1], gf0, gf1);
            unpk(acc[t][bp][2], gg0, gg1);
            unpk(acc[t][bp][3], go0, go1);
            float ai = b ? gi1 : gi0;
            float af = b ? gf1 : gf0;
            float ag = b ? gg1 : gg0;
            float ao = b ? go1 : go0;
            float ig = sigm(ai), fg = sigm(af);
            float gg = tanh_f(ag), og = sigm(ao);
            c1[bi] = fg * c1[bi] + ig * gg;
            float h = og * tanh_f(c1[bi]);
            o1[t][bi] = h;
            scrH[bp * 64 + lane * 2 + b] = h;
        }
        __syncwarp();
    }

    // ---- LN1 + LeakyReLU + residual + head ----
#pragma unroll
    for (int bi = 0; bi < NB; bi++) {
        int bp = bi >> 1, b = bi & 1;
        float s = 0.f, sq = 0.f;
#pragma unroll
        for (int t = 0; t < TT; t++) {
            float v = o1[t][bi];
            s += v; sq += v * v;
        }
#pragma unroll
        for (int off = 16; off > 0; off >>= 1) {
            s  += __shfl_xor_sync(FULL, s,  off);
            sq += __shfl_xor_sync(FULL, sq, off);
        }
        float mu  = s * (1.0f / 160.0f);
        float var = sq * (1.0f / 160.0f) - mu * mu;
        float rs  = rsqrtf(var + 1e-5f);

        float p0 = 0.f, p1 = 0.f, p2 = 0.f;
#pragma unroll
        for (int t = 0; t < TT; t++) {
            int idx = t * 32 + lane;
            float y = (o1[t][bi] - mu) * rs * sG1[idx] + sBe1[idx];
            float o = lrelu(y) + scrO0[t * 128 + bp * 64 + lane * 2 + b];
            p0 += o * sDW[idx];
            p1 += o * sDW[160 + idx];
            p2 += o * sDW[320 + idx];
        }
#pragma unroll
        for (int off = 16; off > 0; off >>= 1) {
            p0 += __shfl_xor_sync(FULL, p0, off);
            p1 += __shfl_xor_sync(FULL, p1, off);
            p2 += __shfl_xor_sync(FULL, p2, off);
        }
        if (lane < 3) {
            float pv = (lane == 0) ? p0 : ((lane == 1) ? p1 : p2);
            pv += sDB[lane];
            out[(base + bi) * 3 + lane] = lrelu(pv);
        }
    }
}

extern "C" void kernel_launch(void* const* d_in, const int* in_sizes, int n_in,
                              void* d_out, int out_size) {
    const float* data  = (const float*)d_in[0];
    const float* w_ih0 = (const float*)d_in[1];
    const float* w_hh0 = (const float*)d_in[2];
    const float* b_ih0 = (const float*)d_in[3];
    const float* b_hh0 = (const float*)d_in[4];
    const float* g0    = (const float*)d_in[5];
    const float* be0   = (const float*)d_in[6];
    const float* w_ih1 = (const float*)d_in[7];
    const float* w_hh1 = (const float*)d_in[8];
    const float* b_ih1 = (const float*)d_in[9];
    const float* b_hh1 = (const float*)d_in[10];
    const float* g1    = (const float*)d_in[11];
    const float* be1   = (const float*)d_in[12];
    const float* dw    = (const float*)d_in[13];
    const float* db    = (const float*)d_in[14];
    float* out = (float*)d_out;

    cudaFuncSetAttribute(reslstm_kernel,
                         cudaFuncAttributeMaxDynamicSharedMemorySize, SMEM_BYTES);

    prep_kernel<<<12, 256>>>(w_ih0, w_ih1);

    int grid = B_TOTAL / (NWARP * NB);   // 8192
    reslstm_kernel<<<grid, NT, SMEM_BYTES>>>(
        data, w_hh0, b_ih0, b_hh0, g0, be0,
        w_hh1, b_ih1, b_hh1, g1, be1, dw, db, out);
}

// round 7
// speedup vs baseline: 1.0422x; 1.0422x over previous
#include <cuda_runtime.h>

// ResLSTM on GB300, round 7: R5 structure (fp32, hoisted input GEMVs) with
// occupancy raised to 16 warps/SM:
//  - 256-thread CTAs (8 warps) share one 38KB weight block -> smem/CTA 104KB
//    -> 2 CTAs/SM; __launch_bounds__(256,2) caps regs at 128.
//  - o1 lives in per-warp smem (reuses dead X region) to fit the reg cap.
//  - warp = 4 batches, lane = hidden unit j; input-phase weights streamed
//    from prep-transposed __device__ arrays, reused over 5 t x 4 batches.

#define WARPS   8
#define NT      (WARPS * 32)
#define NB      4
#define B_TOTAL 131072
#define TT      5
#define NF      62

typedef unsigned long long ull;

// pre-transposed input weights: [row][j*4+g]
__device__ __align__(16) float g_WI0T[64 * 128];   // rows 62,63 zero-padded
__device__ __align__(16) float g_WI1T[32 * 128];

// ---- shared layout (floats) ----
#define OFF_WH0 0                      // 32*128 recurrent L0
#define OFF_W1R (OFF_WH0 + 32*128)     // 32*128 recurrent L1
#define OFF_B0  (OFF_W1R + 32*128)     // 128 (interleaved j*4+g)
#define OFF_B1  (OFF_B0 + 128)
#define OFF_G0  (OFF_B1 + 128)
#define OFF_BE0 (OFF_G0 + 160)
#define OFF_G1  (OFF_BE0 + 160)
#define OFF_BE1 (OFF_G1 + 160)
#define OFF_DW  (OFF_BE1 + 160)        // 480
#define OFF_DB  (OFF_DW + 480)         // 4
#define OFF_SCR (OFF_DB + 4)
// per-warp scratch (floats):
//   X  [bi][t][64] = 1280   (dead after layer-0 phase A; o1 reuses [0..639])
//   H  [bi][32]    = 128
//   O0 [t][bi][32] = 640
#define SCR_W   2048
#define SMEM_FLOATS (OFF_SCR + WARPS * SCR_W)
#define SMEM_BYTES  (SMEM_FLOATS * 4)

__device__ __forceinline__ float tanh_f(float x) {
    float y; asm("tanh.approx.f32 %0, %1;" : "=f"(y) : "f"(x)); return y;
}
__device__ __forceinline__ float sigm(float x) {
    return fmaf(0.5f, tanh_f(0.5f * x), 0.5f);
}
__device__ __forceinline__ float lrelu(float x) {
    return x > 0.0f ? x : 0.01f * x;
}
__device__ __forceinline__ ull pk2(float x) {
    ull r; asm("mov.b64 %0, {%1, %2};" : "=l"(r) : "f"(x), "f"(x)); return r;
}
__device__ __forceinline__ void fma2(ull& d, ull a, ull b) {
    asm("fma.rn.f32x2 %0, %1, %2, %0;" : "+l"(d) : "l"(a), "l"(b));
}
__device__ __forceinline__ void unpk(ull v, float& lo, float& hi) {
    asm("mov.b64 {%0, %1}, %2;" : "=f"(lo), "=f"(hi) : "l"(v));
}

// ---------------- prep: transpose input weights into [row][j*4+g] ----------
__global__ void prep_kernel(const float* __restrict__ w_ih0,
                            const float* __restrict__ w_ih1) {
    for (int i = blockIdx.x * blockDim.x + threadIdx.x; i < 64 * 128;
         i += blockDim.x * gridDim.x) {
        int n = i >> 7, rem = i & 127, j = rem >> 2, g = rem & 3;
        g_WI0T[i] = (n < NF) ? w_ih0[(g * 32 + j) * NF + n] : 0.0f;
        if (n < 32) g_WI1T[i] = w_ih1[(g * 32 + j) * 32 + n];
    }
}

// input-phase: stream nG weight groups once, reuse across (t, bi) from regs
__device__ __forceinline__ void phaseA(
    const float* __restrict__ Wg, const float* __restrict__ vec,
    int bistride, int tstride, int nG, int lane,
    ull xg01[TT][NB], ull xg23[TT][NB])
{
#pragma unroll 1
    for (int g = 0; g < nG; g++) {
        const ulonglong2* w = (const ulonglong2*)(Wg + g * 512) + lane;
        ulonglong2 w0 = w[0], w1 = w[32], w2 = w[64], w3 = w[96];
        const float* vg = vec + g * 4;
#pragma unroll
        for (int t = 0; t < TT; t++) {
#pragma unroll
            for (int bi = 0; bi < NB; bi++) {
                float4 xv = *(const float4*)(vg + bi * bistride + t * tstride);
                ull xp;
                xp = pk2(xv.x); fma2(xg01[t][bi], xp, w0.x); fma2(xg23[t][bi], xp, w0.y);
                xp = pk2(xv.y); fma2(xg01[t][bi], xp, w1.x); fma2(xg23[t][bi], xp, w1.y);
                xp = pk2(xv.z); fma2(xg01[t][bi], xp, w2.x); fma2(xg23[t][bi], xp, w2.y);
                xp = pk2(xv.w); fma2(xg01[t][bi], xp, w3.x); fma2(xg23[t][bi], xp, w3.y);
            }
        }
    }
}

// recurrent-phase: one 4-row group from smem weights against h (per-warp smem)
__device__ __forceinline__ void phaseB_group(
    const float* __restrict__ Wsm, const float* __restrict__ hvec,
    int g, int lane, ull a01[NB], ull a23[NB])
{
    const ulonglong2* w = (const ulonglong2*)(Wsm + g * 512) + lane;
    ulonglong2 w0 = w[0], w1 = w[32], w2 = w[64], w3 = w[96];
#pragma unroll
    for (int bi = 0; bi < NB; bi++) {
        float4 hv = *(const float4*)(hvec + bi * 32 + g * 4);
        ull xp;
        xp = pk2(hv.x); fma2(a01[bi], xp, w0.x); fma2(a23[bi], xp, w0.y);
        xp = pk2(hv.y); fma2(a01[bi], xp, w1.x); fma2(a23[bi], xp, w1.y);
        xp = pk2(hv.z); fma2(a01[bi], xp, w2.x); fma2(a23[bi], xp, w2.y);
        xp = pk2(hv.w); fma2(a01[bi], xp, w3.x); fma2(a23[bi], xp, w3.y);
    }
}

__global__ __launch_bounds__(NT, 2) void reslstm_kernel(
    const float* __restrict__ data,
    const float* __restrict__ w_hh0,
    const float* __restrict__ b_ih0, const float* __restrict__ b_hh0,
    const float* __restrict__ g0,    const float* __restrict__ be0,
    const float* __restrict__ w_hh1,
    const float* __restrict__ b_ih1, const float* __restrict__ b_hh1,
    const float* __restrict__ g1,    const float* __restrict__ be1,
    const float* __restrict__ dw,    const float* __restrict__ db,
    float* __restrict__ out)
{
    extern __shared__ float sm[];
    float* sWH0 = sm + OFF_WH0;
    float* sW1R = sm + OFF_W1R;
    float* sB0  = sm + OFF_B0;
    float* sB1  = sm + OFF_B1;
    float* sG0  = sm + OFF_G0;
    float* sBe0 = sm + OFF_BE0;
    float* sG1  = sm + OFF_G1;
    float* sBe1 = sm + OFF_BE1;
    float* sDW  = sm + OFF_DW;
    float* sDB  = sm + OFF_DB;

    const int tid  = threadIdx.x;
    const int lane = tid & 31;
    const int wid  = tid >> 5;

    // stage recurrent weights transposed+interleaved [k][j*4+g]
    for (int i = tid; i < 32 * 128; i += NT) {
        int k = i >> 7, rem = i & 127, j = rem >> 2, g = rem & 3;
        sWH0[i] = w_hh0[(g * 32 + j) * 32 + k];
        sW1R[i] = w_hh1[(g * 32 + j) * 32 + k];
    }
    for (int i = tid; i < 128; i += NT) {
        int j = i >> 2, g = i & 3;
        sB0[i] = b_ih0[g * 32 + j] + b_hh0[g * 32 + j];
        sB1[i] = b_ih1[g * 32 + j] + b_hh1[g * 32 + j];
    }
    for (int i = tid; i < 160; i += NT) {
        sG0[i] = g0[i]; sBe0[i] = be0[i];
        sG1[i] = g1[i]; sBe1[i] = be1[i];
    }
    for (int i = tid; i < 480; i += NT) sDW[i] = dw[i];
    if (tid < 3) sDB[tid] = db[tid];

    float* scrX  = sm + OFF_SCR + wid * SCR_W;  // [bi*320 + t*64 + n]
    float* scrH  = scrX + 1280;                 // [bi*32 + k]
    float* scrO0 = scrH + 128;                  // [t*128 + bi*32 + j]
    float* scrO1 = scrX;                        // o1 reuses X after L0 phase A

    const long long base = ((long long)blockIdx.x * WARPS + wid) * NB;

    // stage X for all t (pad n=62,63 with 0); init h=0
#pragma unroll
    for (int bi = 0; bi < NB; bi++) {
        const float* dp = data + (base + bi) * (NF * TT);
#pragma unroll
        for (int t = 0; t < TT; t++) {
            scrX[bi * 320 + t * 64 + lane] = __ldg(dp + lane * TT + t);
            if (lane < NF - 32)
                scrX[bi * 320 + t * 64 + 32 + lane] = __ldg(dp + (lane + 32) * TT + t);
        }
        if (lane < 2) {
#pragma unroll
            for (int t = 0; t < TT; t++)
                scrX[bi * 320 + t * 64 + 62 + lane] = 0.0f;
        }
        scrH[bi * 32 + lane] = 0.0f;
    }
    __syncthreads();

    const unsigned FULL = 0xffffffffu;
    ulonglong2 b0p = ((const ulonglong2*)sB0)[lane];

    // ======== layer 0: input phase (hoisted over t) ========
    ull xg01[TT][NB], xg23[TT][NB];
#pragma unroll
    for (int t = 0; t < TT; t++)
#pragma unroll
        for (int bi = 0; bi < NB; bi++) { xg01[t][bi] = b0p.x; xg23[t][bi] = b0p.y; }

    phaseA(g_WI0T, scrX, 320, 64, 16, lane, xg01, xg23);

    // ======== layer 0: recurrent phase ========
    float c0[NB];
#pragma unroll
    for (int bi = 0; bi < NB; bi++) c0[bi] = 0.f;

#pragma unroll
    for (int t = 0; t < TT; t++) {
#pragma unroll 1
        for (int g = 0; g < 8; g++)
            phaseB_group(sWH0, scrH, g, lane, xg01[t], xg23[t]);
#pragma unroll
        for (int bi = 0; bi < NB; bi++) {
            float ai, af, ag, ao;
            unpk(xg01[t][bi], ai, af);
            unpk(xg23[t][bi], ag, ao);
            float ig = sigm(ai), fg = sigm(af);
            float gg = tanh_f(ag), og = sigm(ao);
            c0[bi] = fg * c0[bi] + ig * gg;
            float h = og * tanh_f(c0[bi]);
            scrH[bi * 32 + lane] = h;
            scrO0[t * 128 + bi * 32 + lane] = h;
        }
        __syncwarp();
    }

    // ---- LN0 + LeakyReLU (in place in scrO0) ----
#pragma unroll
    for (int bi = 0; bi < NB; bi++) {
        float v[TT];
        float s = 0.f, sq = 0.f;
#pragma unroll
        for (int t = 0; t < TT; t++) {
            v[t] = scrO0[t * 128 + bi * 32 + lane];
            s += v[t]; sq += v[t] * v[t];
        }
#pragma unroll
        for (int off = 16; off > 0; off >>= 1) {
            s  += __shfl_xor_sync(FULL, s,  off);
            sq += __shfl_xor_sync(FULL, sq, off);
        }
        float mu  = s * (1.0f / 160.0f);
        float var = sq * (1.0f / 160.0f) - mu * mu;
        float rs  = rsqrtf(var + 1e-5f);
#pragma unroll
        for (int t = 0; t < TT; t++) {
            float y = (v[t] - mu) * rs * sG0[t * 32 + lane] + sBe0[t * 32 + lane];
            scrO0[t * 128 + bi * 32 + lane] = lrelu(y);
        }
        scrH[bi * 32 + lane] = 0.0f;   // reset h for layer 1
    }
    __syncwarp();

    // ======== layer 1: input phase (over post-LN o0, hoisted over t) ========
    ulonglong2 b1p = ((const ulonglong2*)sB1)[lane];
#pragma unroll
    for (int t = 0; t < TT; t++)
#pragma unroll
        for (int bi = 0; bi < NB; bi++) { xg01[t][bi] = b1p.x; xg23[t][bi] = b1p.y; }

    phaseA(g_WI1T, scrO0, 32, 128, 8, lane, xg01, xg23);

    // ======== layer 1: recurrent phase ========
    float c1[NB];
#pragma unroll
    for (int bi = 0; bi < NB; bi++) c1[bi] = 0.f;

#pragma unroll
    for (int t = 0; t < TT; t++) {
#pragma unroll 1
        for (int g = 0; g < 8; g++)
            phaseB_group(sW1R, scrH, g, lane, xg01[t], xg23[t]);
#pragma unroll
        for (int bi = 0; bi < NB; bi++) {
            float ai, af, ag, ao;
            unpk(xg01[t][bi], ai, af);
            unpk(xg23[t][bi], ag, ao);
            float ig = sigm(ai), fg = sigm(af);
            float gg = tanh_f(ag), og = sigm(ao);
            c1[bi] = fg * c1[bi] + ig * gg;
            float h = og * tanh_f(c1[bi]);
            scrH[bi * 32 + lane] = h;
            scrO1[t * 128 + bi * 32 + lane] = h;
        }
        __syncwarp();
    }

    // ---- LN1 + LeakyReLU + residual + head ----
#pragma unroll
    for (int bi = 0; bi < NB; bi++) {
        float v[TT];
        float s = 0.f, sq = 0.f;
#pragma unroll
        for (int t = 0; t < TT; t++) {
            v[t] = scrO1[t * 128 + bi * 32 + lane];
            s += v[t]; sq += v[t] * v[t];
        }
#pragma unroll
        for (int off = 16; off > 0; off >>= 1) {
            s  += __shfl_xor_sync(FULL, s,  off);
            sq += __shfl_xor_sync(FULL, sq, off);
        }
        float mu  = s * (1.0f / 160.0f);
        float var = sq * (1.0f / 160.0f) - mu * mu;
        float rs  = rsqrtf(var + 1e-5f);

        float p0 = 0.f, p1 = 0.f, p2 = 0.f;
#pragma unroll
        for (int t = 0; t < TT; t++) {
            int idx = t * 32 + lane;
            float y = (v[t] - mu) * rs * sG1[idx] + sBe1[idx];
            float o = lrelu(y) + scrO0[t * 128 + bi * 32 + lane];
            p0 += o * sDW[idx];
            p1 += o * sDW[160 + idx];
            p2 += o * sDW[320 + idx];
        }
#pragma unroll
        for (int off = 16; off > 0; off >>= 1) {
            p0 += __shfl_xor_sync(FULL, p0, off);
            p1 += __shfl_xor_sync(FULL, p1, off);
            p2 += __shfl_xor_sync(FULL, p2, off);
        }
        if (lane < 3) {
            float pv = (lane == 0) ? p0 : ((lane == 1) ? p1 : p2);
            pv += sDB[lane];
            out[(base + bi) * 3 + lane] = lrelu(pv);
        }
    }
}

extern "C" void kernel_launch(void* const* d_in, const int* in_sizes, int n_in,
                              void* d_out, int out_size) {
    const float* data  = (const float*)d_in[0];
    const float* w_ih0 = (const float*)d_in[1];
    const float* w_hh0 = (const float*)d_in[2];
    const float* b_ih0 = (const float*)d_in[3];
    const float* b_hh0 = (const float*)d_in[4];
    const float* g0    = (const float*)d_in[5];
    const float* be0   = (const float*)d_in[6];
    const float* w_ih1 = (const float*)d_in[7];
    const float* w_hh1 = (const float*)d_in[8];
    const float* b_ih1 = (const float*)d_in[9];
    const float* b_hh1 = (const float*)d_in[10];
    const float* g1    = (const float*)d_in[11];
    const float* be1   = (const float*)d_in[12];
    const float* dw    = (const float*)d_in[13];
    const float* db    = (const float*)d_in[14];
    float* out = (float*)d_out;

    cudaFuncSetAttribute(reslstm_kernel,
                         cudaFuncAttributeMaxDynamicSharedMemorySize, SMEM_BYTES);

    prep_kernel<<<12, 256>>>(w_ih0, w_ih1);

    int grid = B_TOTAL / (WARPS * NB);   // 4096
    reslstm_kernel<<<grid, NT, SMEM_BYTES>>>(
        data, w_hh0, b_ih0, b_hh0, g0, be0,
        w_hh1, b_ih1, b_hh1, g1, be1, dw, db, out);
}

// round 8
// speedup vs baseline: 1.0922x; 1.0480x over previous
#include <cuda_runtime.h>

// ResLSTM on GB300, round 8: R7 + batch-pair f32x2 packing in pure fp32.
//  - acc[t][bp][gate] = f32x2 (batch b0, batch b1): operands naturally packed
//    in smem ([..][n][2] layouts), weights pk2-duplicated ONCE per load and
//    reused across 5 timesteps x 2 batch-pairs (phase A) / 2 pairs (phase B).
//  - kills ~1500 per-iteration pk2 movs/warp vs R7 at identical L1 bytes.
//  - 256-thr CTAs, 2 CTAs/SM (16 warps/SM), regs capped 128.

#define WARPS   8
#define NT      (WARPS * 32)
#define NB      4
#define B_TOTAL 131072
#define TT      5
#define NF      62

typedef unsigned long long ull;

// pre-transposed input weights: [row][j*4+g]
__device__ __align__(16) float g_WI0T[64 * 128];   // rows 62,63 zero-padded
__device__ __align__(16) float g_WI1T[32 * 128];

// ---- shared layout (floats) ----
#define OFF_WH0 0                      // 32*128 recurrent L0
#define OFF_W1R (OFF_WH0 + 32*128)     // 32*128 recurrent L1
#define OFF_B0  (OFF_W1R + 32*128)     // 128 (interleaved j*4+g)
#define OFF_B1  (OFF_B0 + 128)
#define OFF_G0  (OFF_B1 + 128)
#define OFF_BE0 (OFF_G0 + 160)
#define OFF_G1  (OFF_BE0 + 160)
#define OFF_BE1 (OFF_G1 + 160)
#define OFF_DW  (OFF_BE1 + 160)        // 480
#define OFF_DB  (OFF_DW + 480)         // 4
#define OFF_SCR (OFF_DB + 4)
// per-warp scratch (floats):
//   X  [t][bp][n][2]  = 5*2*64*2 = 1280  (dead after L0 phase A; O1 reuses it)
//   H  [bp][k][2]     = 128
//   O0 [t][bp][j][2]  = 640
#define SCR_W   2048
#define SMEM_FLOATS (OFF_SCR + WARPS * SCR_W)
#define SMEM_BYTES  (SMEM_FLOATS * 4)

__device__ __forceinline__ float tanh_f(float x) {
    float y; asm("tanh.approx.f32 %0, %1;" : "=f"(y) : "f"(x)); return y;
}
__device__ __forceinline__ float sigm(float x) {
    return fmaf(0.5f, tanh_f(0.5f * x), 0.5f);
}
__device__ __forceinline__ float lrelu(float x) {
    return x > 0.0f ? x : 0.01f * x;
}
__device__ __forceinline__ ull pk2(float x) {
    ull r; asm("mov.b64 %0, {%1, %2};" : "=l"(r) : "f"(x), "f"(x)); return r;
}
__device__ __forceinline__ void fma2(ull& d, ull a, ull b) {
    asm("fma.rn.f32x2 %0, %1, %2, %0;" : "+l"(d) : "l"(a), "l"(b));
}
__device__ __forceinline__ void unpk(ull v, float& lo, float& hi) {
    asm("mov.b64 {%0, %1}, %2;" : "=f"(lo), "=f"(hi) : "l"(v));
}

// ---------------- prep: transpose input weights into [row][j*4+g] ----------
__global__ void prep_kernel(const float* __restrict__ w_ih0,
                            const float* __restrict__ w_ih1) {
    for (int i = blockIdx.x * blockDim.x + threadIdx.x; i < 64 * 128;
         i += blockDim.x * gridDim.x) {
        int n = i >> 7, rem = i & 127, j = rem >> 2, g = rem & 3;
        g_WI0T[i] = (n < NF) ? w_ih0[(g * 32 + j) * NF + n] : 0.0f;
        if (n < 32) g_WI1T[i] = w_ih1[(g * 32 + j) * 32 + n];
    }
}

// input-phase: stream nG weight groups once, duplicate once, reuse across
// 5 timesteps x 2 batch-pairs. Operands are naturally bp-packed in smem.
__device__ __forceinline__ void phaseA(
    const float* __restrict__ Wg, const float* __restrict__ vec,
    int tstride, int bstride, int nG, int lane, ull acc[TT][2][4])
{
#pragma unroll 1
    for (int g = 0; g < nG; g++) {
        const float4* wrow = (const float4*)(Wg + g * 512) + lane;
#pragma unroll
        for (int half = 0; half < 2; half++) {
            float4 wa = wrow[half * 64];        // row 4g+2h
            float4 wb = wrow[half * 64 + 32];   // row 4g+2h+1
            ull wd0 = pk2(wa.x), wd1 = pk2(wa.y), wd2 = pk2(wa.z), wd3 = pk2(wa.w);
            ull we0 = pk2(wb.x), we1 = pk2(wb.y), we2 = pk2(wb.z), we3 = pk2(wb.w);
#pragma unroll
            for (int t = 0; t < TT; t++) {
#pragma unroll
                for (int bp = 0; bp < 2; bp++) {
                    ulonglong2 x = *(const ulonglong2*)
                        (vec + t * tstride + bp * bstride + g * 8 + half * 4);
                    fma2(acc[t][bp][0], x.x, wd0);
                    fma2(acc[t][bp][1], x.x, wd1);
                    fma2(acc[t][bp][2], x.x, wd2);
                    fma2(acc[t][bp][3], x.x, wd3);
                    fma2(acc[t][bp][0], x.y, we0);
                    fma2(acc[t][bp][1], x.y, we1);
                    fma2(acc[t][bp][2], x.y, we2);
                    fma2(acc[t][bp][3], x.y, we3);
                }
            }
        }
    }
}

// recurrent-phase: one 4-row group from smem weights against bp-packed h
__device__ __forceinline__ void phaseB_group(
    const float* __restrict__ Wsm, const float* __restrict__ hvec,
    int g, int lane, ull acc[2][4])
{
    const float4* wrow = (const float4*)(Wsm + g * 512) + lane;
#pragma unroll
    for (int half = 0; half < 2; half++) {
        float4 wa = wrow[half * 64];
        float4 wb = wrow[half * 64 + 32];
        ull wd0 = pk2(wa.x), wd1 = pk2(wa.y), wd2 = pk2(wa.z), wd3 = pk2(wa.w);
        ull we0 = pk2(wb.x), we1 = pk2(wb.y), we2 = pk2(wb.z), we3 = pk2(wb.w);
#pragma unroll
        for (int bp = 0; bp < 2; bp++) {
            ulonglong2 h = *(const ulonglong2*)(hvec + bp * 64 + g * 8 + half * 4);
            fma2(acc[bp][0], h.x, wd0);
            fma2(acc[bp][1], h.x, wd1);
            fma2(acc[bp][2], h.x, wd2);
            fma2(acc[bp][3], h.x, wd3);
            fma2(acc[bp][0], h.y, we0);
            fma2(acc[bp][1], h.y, we1);
            fma2(acc[bp][2], h.y, we2);
            fma2(acc[bp][3], h.y, we3);
        }
    }
}

__global__ __launch_bounds__(NT, 2) void reslstm_kernel(
    const float* __restrict__ data,
    const float* __restrict__ w_hh0,
    const float* __restrict__ b_ih0, const float* __restrict__ b_hh0,
    const float* __restrict__ g0,    const float* __restrict__ be0,
    const float* __restrict__ w_hh1,
    const float* __restrict__ b_ih1, const float* __restrict__ b_hh1,
    const float* __restrict__ g1,    const float* __restrict__ be1,
    const float* __restrict__ dw,    const float* __restrict__ db,
    float* __restrict__ out)
{
    extern __shared__ float sm[];
    float* sWH0 = sm + OFF_WH0;
    float* sW1R = sm + OFF_W1R;
    float* sB0  = sm + OFF_B0;
    float* sB1  = sm + OFF_B1;
    float* sG0  = sm + OFF_G0;
    float* sBe0 = sm + OFF_BE0;
    float* sG1  = sm + OFF_G1;
    float* sBe1 = sm + OFF_BE1;
    float* sDW  = sm + OFF_DW;
    float* sDB  = sm + OFF_DB;

    const int tid  = threadIdx.x;
    const int lane = tid & 31;
    const int wid  = tid >> 5;

    // stage recurrent weights transposed+interleaved [k][j*4+g]
    for (int i = tid; i < 32 * 128; i += NT) {
        int k = i >> 7, rem = i & 127, j = rem >> 2, g = rem & 3;
        sWH0[i] = w_hh0[(g * 32 + j) * 32 + k];
        sW1R[i] = w_hh1[(g * 32 + j) * 32 + k];
    }
    for (int i = tid; i < 128; i += NT) {
        int j = i >> 2, g = i & 3;
        sB0[i] = b_ih0[g * 32 + j] + b_hh0[g * 32 + j];
        sB1[i] = b_ih1[g * 32 + j] + b_hh1[g * 32 + j];
    }
    for (int i = tid; i < 160; i += NT) {
        sG0[i] = g0[i]; sBe0[i] = be0[i];
        sG1[i] = g1[i]; sBe1[i] = be1[i];
    }
    for (int i = tid; i < 480; i += NT) sDW[i] = dw[i];
    if (tid < 3) sDB[tid] = db[tid];

    float* scrX  = sm + OFF_SCR + wid * SCR_W;  // [t*256 + bp*128 + n*2 + b]
    float* scrH  = scrX + 1280;                 // [bp*64 + k*2 + b]
    float* scrO0 = scrH + 128;                  // [t*128 + bp*64 + j*2 + b]
    float* scrO1 = scrX;                        // reuses X after L0 phase A

    const long long base = ((long long)blockIdx.x * WARPS + wid) * NB;

    // stage X (bp-packed; pad n=62,63 with 0); init h=0
#pragma unroll
    for (int bi = 0; bi < NB; bi++) {
        int bp = bi >> 1, b = bi & 1;
        const float* dp = data + (base + bi) * (NF * TT);
        float* xw = scrX + bp * 128 + b;
#pragma unroll
        for (int t = 0; t < TT; t++) {
            xw[t * 256 + lane * 2] = __ldg(dp + lane * TT + t);
            if (lane < NF - 32)
                xw[t * 256 + (lane + 32) * 2] = __ldg(dp + (lane + 32) * TT + t);
        }
        if (lane < 2) {
#pragma unroll
            for (int t = 0; t < TT; t++)
                xw[t * 256 + (62 + lane) * 2] = 0.0f;
        }
    }
    scrH[lane] = 0.0f; scrH[32 + lane] = 0.0f;
    scrH[64 + lane] = 0.0f; scrH[96 + lane] = 0.0f;
    __syncthreads();

    const unsigned FULL = 0xffffffffu;

    // ======== layer 0: input phase (hoisted over t) ========
    ull acc[TT][2][4];
    {
        float4 b0q = *(const float4*)(sB0 + lane * 4);
        ull bd0 = pk2(b0q.x), bd1 = pk2(b0q.y), bd2 = pk2(b0q.z), bd3 = pk2(b0q.w);
#pragma unroll
        for (int t = 0; t < TT; t++)
#pragma unroll
            for (int bp = 0; bp < 2; bp++) {
                acc[t][bp][0] = bd0; acc[t][bp][1] = bd1;
                acc[t][bp][2] = bd2; acc[t][bp][3] = bd3;
            }
    }
    phaseA(g_WI0T, scrX, 256, 128, 16, lane, acc);

    // ======== layer 0: recurrent phase ========
    float c0[NB];
#pragma unroll
    for (int bi = 0; bi < NB; bi++) c0[bi] = 0.f;

#pragma unroll
    for (int t = 0; t < TT; t++) {
#pragma unroll 1
        for (int g = 0; g < 8; g++)
            phaseB_group(sWH0, scrH, g, lane, acc[t]);
#pragma unroll
        for (int bp = 0; bp < 2; bp++) {
            float i0, i1, f0, f1, gv0, gv1, o0v, o1v;
            unpk(acc[t][bp][0], i0, i1);
            unpk(acc[t][bp][1], f0, f1);
            unpk(acc[t][bp][2], gv0, gv1);
            unpk(acc[t][bp][3], o0v, o1v);
            {   // batch b=0
                int bi = bp * 2;
                float ig = sigm(i0), fg = sigm(f0), gg = tanh_f(gv0), og = sigm(o0v);
                c0[bi] = fg * c0[bi] + ig * gg;
                float h = og * tanh_f(c0[bi]);
                scrH[bp * 64 + lane * 2] = h;
                scrO0[t * 128 + bp * 64 + lane * 2] = h;
            }
            {   // batch b=1
                int bi = bp * 2 + 1;
                float ig = sigm(i1), fg = sigm(f1), gg = tanh_f(gv1), og = sigm(o1v);
                c0[bi] = fg * c0[bi] + ig * gg;
                float h = og * tanh_f(c0[bi]);
                scrH[bp * 64 + lane * 2 + 1] = h;
                scrO0[t * 128 + bp * 64 + lane * 2 + 1] = h;
            }
        }
        __syncwarp();
    }

    // ---- LN0 + LeakyReLU (in place in scrO0) ----
#pragma unroll
    for (int bi = 0; bi < NB; bi++) {
        int bp = bi >> 1, b = bi & 1;
        float v[TT];
        float s = 0.f, sq = 0.f;
#pragma unroll
        for (int t = 0; t < TT; t++) {
            v[t] = scrO0[t * 128 + bp * 64 + lane * 2 + b];
            s += v[t]; sq += v[t] * v[t];
        }
#pragma unroll
        for (int off = 16; off > 0; off >>= 1) {
            s  += __shfl_xor_sync(FULL, s,  off);
            sq += __shfl_xor_sync(FULL, sq, off);
        }
        float mu  = s * (1.0f / 160.0f);
        float var = sq * (1.0f / 160.0f) - mu * mu;
        float rs  = rsqrtf(var + 1e-5f);
#pragma unroll
        for (int t = 0; t < TT; t++) {
            float y = (v[t] - mu) * rs * sG0[t * 32 + lane] + sBe0[t * 32 + lane];
            scrO0[t * 128 + bp * 64 + lane * 2 + b] = lrelu(y);
        }
    }
    scrH[lane] = 0.0f; scrH[32 + lane] = 0.0f;
    scrH[64 + lane] = 0.0f; scrH[96 + lane] = 0.0f;   // reset h for layer 1
    __syncwarp();

    // ======== layer 1: input phase over post-LN o0 ========
    {
        float4 b1q = *(const float4*)(sB1 + lane * 4);
        ull bd0 = pk2(b1q.x), bd1 = pk2(b1q.y), bd2 = pk2(b1q.z), bd3 = pk2(b1q.w);
#pragma unroll
        for (int t = 0; t < TT; t++)
#pragma unroll
            for (int bp = 0; bp < 2; bp++) {
                acc[t][bp][0] = bd0; acc[t][bp][1] = bd1;
                acc[t][bp][2] = bd2; acc[t][bp][3] = bd3;
            }
    }
    phaseA(g_WI1T, scrO0, 128, 64, 8, lane, acc);

    // ======== layer 1: recurrent phase ========
    float c1[NB];
#pragma unroll
    for (int bi = 0; bi < NB; bi++) c1[bi] = 0.f;

#pragma unroll
    for (int t = 0; t < TT; t++) {
#pragma unroll 1
        for (int g = 0; g < 8; g++)
            phaseB_group(sW1R, scrH, g, lane, acc[t]);
#pragma unroll
        for (int bp = 0; bp < 2; bp++) {
            float i0, i1, f0, f1, gv0, gv1, o0v, o1v;
            unpk(acc[t][bp][0], i0, i1);
            unpk(acc[t][bp][1], f0, f1);
            unpk(acc[t][bp][2], gv0, gv1);
            unpk(acc[t][bp][3], o0v, o1v);
            {   // batch b=0
                int bi = bp * 2;
                float ig = sigm(i0), fg = sigm(f0), gg = tanh_f(gv0), og = sigm(o0v);
                c1[bi] = fg * c1[bi] + ig * gg;
                float h = og * tanh_f(c1[bi]);
                scrH[bp * 64 + lane * 2] = h;
                scrO1[t * 128 + bp * 64 + lane * 2] = h;
            }
            {   // batch b=1
                int bi = bp * 2 + 1;
                float ig = sigm(i1), fg = sigm(f1), gg = tanh_f(gv1), og = sigm(o1v);
                c1[bi] = fg * c1[bi] + ig * gg;
                float h = og * tanh_f(c1[bi]);
                scrH[bp * 64 + lane * 2 + 1] = h;
                scrO1[t * 128 + bp * 64 + lane * 2 + 1] = h;
            }
        }
        __syncwarp();
    }

    // ---- LN1 + LeakyReLU + residual + head ----
#pragma unroll
    for (int bi = 0; bi < NB; bi++) {
        int bp = bi >> 1, b = bi & 1;
        float v[TT];
        float s = 0.f, sq = 0.f;
#pragma unroll
        for (int t = 0; t < TT; t++) {
            v[t] = scrO1[t * 128 + bp * 64 + lane * 2 + b];
            s += v[t]; sq += v[t] * v[t];
        }
#pragma unroll
        for (int off = 16; off > 0; off >>= 1) {
            s  += __shfl_xor_sync(FULL, s,  off);
            sq += __shfl_xor_sync(FULL, sq, off);
        }
        float mu  = s * (1.0f / 160.0f);
        float var = sq * (1.0f / 160.0f) - mu * mu;
        float rs  = rsqrtf(var + 1e-5f);

        float p0 = 0.f, p1 = 0.f, p2 = 0.f;
#pragma unroll
        for (int t = 0; t < TT; t++) {
            int idx = t * 32 + lane;
            float y = (v[t] - mu) * rs * sG1[idx] + sBe1[idx];
            float o = lrelu(y) + scrO0[t * 128 + bp * 64 + lane * 2 + b];
            p0 += o * sDW[idx];
            p1 += o * sDW[160 + idx];
            p2 += o * sDW[320 + idx];
        }
#pragma unroll
        for (int off = 16; off > 0; off >>= 1) {
            p0 += __shfl_xor_sync(FULL, p0, off);
            p1 += __shfl_xor_sync(FULL, p1, off);
            p2 += __shfl_xor_sync(FULL, p2, off);
        }
        if (lane < 3) {
            float pv = (lane == 0) ? p0 : ((lane == 1) ? p1 : p2);
            pv += sDB[lane];
            out[(base + bi) * 3 + lane] = lrelu(pv);
        }
    }
}

extern "C" void kernel_launch(void* const* d_in, const int* in_sizes, int n_in,
                              void* d_out, int out_size) {
    const float* data  = (const float*)d_in[0];
    const float* w_ih0 = (const float*)d_in[1];
    const float* w_hh0 = (const float*)d_in[2];
    const float* b_ih0 = (const float*)d_in[3];
    const float* b_hh0 = (const float*)d_in[4];
    const float* g0    = (const float*)d_in[5];
    const float* be0   = (const float*)d_in[6];
    const float* w_ih1 = (const float*)d_in[7];
    const float* w_hh1 = (const float*)d_in[8];
    const float* b_ih1 = (const float*)d_in[9];
    const float* b_hh1 = (const float*)d_in[10];
    const float* g1    = (const float*)d_in[11];
    const float* be1   = (const float*)d_in[12];
    const float* dw    = (const float*)d_in[13];
    const float* db    = (const float*)d_in[14];
    float* out = (float*)d_out;

    cudaFuncSetAttribute(reslstm_kernel,
                         cudaFuncAttributeMaxDynamicSharedMemorySize, SMEM_BYTES);

    prep_kernel<<<12, 256>>>(w_ih0, w_ih1);

    int grid = B_TOTAL / (WARPS * NB);   // 4096
    reslstm_kernel<<<grid, NT, SMEM_BYTES>>>(
        data, w_hh0, b_ih0, b_hh0, g0, be0,
        w_hh1, b_ih1, b_hh1, g1, be1, dw, db, out);
}

// round 9
// speedup vs baseline: 1.0980x; 1.0053x over previous
#include <cuda_runtime.h>

// ResLSTM on GB300, round 9: R8 + NB=6 (3 batch-pairs per warp).
//  - weight bytes (the dominant L1 term, NB-invariant per warp) amortized
//    over 6 batches instead of 4: L1 wavefronts/batch -22%.
//  - acc[t][bp][gate] f32x2 batch-pairs; 192-thr CTAs x 2 CTAs/SM
//    (12 warps/SM, 168-reg cap, smem 109.4KB/CTA).
//  - B=131072 not divisible by 36/CTA -> grid 3641 + bounds guards.

#define NWARP   6
#define NT      (NWARP * 32)
#define NB      6
#define NBP     3
#define B_TOTAL 131072
#define TT      5
#define NF      62

typedef unsigned long long ull;

// pre-transposed input weights: [row][j*4+g]
__device__ __align__(16) float g_WI0T[64 * 128];   // rows 62,63 zero-padded
__device__ __align__(16) float g_WI1T[32 * 128];

// ---- shared layout (floats) ----
#define OFF_WH0 0                      // 32*128 recurrent L0
#define OFF_W1R (OFF_WH0 + 32*128)     // 32*128 recurrent L1
#define OFF_B0  (OFF_W1R + 32*128)     // 128 (interleaved j*4+g)
#define OFF_B1  (OFF_B0 + 128)
#define OFF_G0  (OFF_B1 + 128)
#define OFF_BE0 (OFF_G0 + 160)
#define OFF_G1  (OFF_BE0 + 160)
#define OFF_BE1 (OFF_G1 + 160)
#define OFF_DW  (OFF_BE1 + 160)        // 480
#define OFF_DB  (OFF_DW + 480)         // 4
#define OFF_SCR (OFF_DB + 4)
// per-warp scratch (floats):
//   X  [t][bp][n][2]  = 5*3*64*2 = 1920  (dead after L0 phase A; O1 reuses)
//   H  [bp][k][2]     = 3*32*2   = 192
//   O0 [t][bp][j][2]  = 5*3*32*2 = 960
#define SCR_W   3072
#define SMEM_FLOATS (OFF_SCR + NWARP * SCR_W)
#define SMEM_BYTES  (SMEM_FLOATS * 4)

__device__ __forceinline__ float tanh_f(float x) {
    float y; asm("tanh.approx.f32 %0, %1;" : "=f"(y) : "f"(x)); return y;
}
__device__ __forceinline__ float sigm(float x) {
    return fmaf(0.5f, tanh_f(0.5f * x), 0.5f);
}
__device__ __forceinline__ float lrelu(float x) {
    return x > 0.0f ? x : 0.01f * x;
}
__device__ __forceinline__ ull pk2(float x) {
    ull r; asm("mov.b64 %0, {%1, %2};" : "=l"(r) : "f"(x), "f"(x)); return r;
}
__device__ __forceinline__ void fma2(ull& d, ull a, ull b) {
    asm("fma.rn.f32x2 %0, %1, %2, %0;" : "+l"(d) : "l"(a), "l"(b));
}
__device__ __forceinline__ void unpk(ull v, float& lo, float& hi) {
    asm("mov.b64 {%0, %1}, %2;" : "=f"(lo), "=f"(hi) : "l"(v));
}

// ---------------- prep: transpose input weights into [row][j*4+g] ----------
__global__ void prep_kernel(const float* __restrict__ w_ih0,
                            const float* __restrict__ w_ih1) {
    for (int i = blockIdx.x * blockDim.x + threadIdx.x; i < 64 * 128;
         i += blockDim.x * gridDim.x) {
        int n = i >> 7, rem = i & 127, j = rem >> 2, g = rem & 3;
        g_WI0T[i] = (n < NF) ? w_ih0[(g * 32 + j) * NF + n] : 0.0f;
        if (n < 32) g_WI1T[i] = w_ih1[(g * 32 + j) * 32 + n];
    }
}

// input-phase: stream nG weight groups once, duplicate once, reuse across
// 5 timesteps x 3 batch-pairs. Operands are naturally bp-packed in smem.
__device__ __forceinline__ void phaseA(
    const float* __restrict__ Wg, const float* __restrict__ vec,
    int tstride, int bstride, int nG, int lane, ull acc[TT][NBP][4])
{
#pragma unroll 1
    for (int g = 0; g < nG; g++) {
        const float4* wrow = (const float4*)(Wg + g * 512) + lane;
#pragma unroll
        for (int half = 0; half < 2; half++) {
            float4 wa = wrow[half * 64];        // row 4g+2h
            float4 wb = wrow[half * 64 + 32];   // row 4g+2h+1
            ull wd0 = pk2(wa.x), wd1 = pk2(wa.y), wd2 = pk2(wa.z), wd3 = pk2(wa.w);
            ull we0 = pk2(wb.x), we1 = pk2(wb.y), we2 = pk2(wb.z), we3 = pk2(wb.w);
#pragma unroll
            for (int t = 0; t < TT; t++) {
#pragma unroll
                for (int bp = 0; bp < NBP; bp++) {
                    ulonglong2 x = *(const ulonglong2*)
                        (vec + t * tstride + bp * bstride + g * 8 + half * 4);
                    fma2(acc[t][bp][0], x.x, wd0);
                    fma2(acc[t][bp][1], x.x, wd1);
                    fma2(acc[t][bp][2], x.x, wd2);
                    fma2(acc[t][bp][3], x.x, wd3);
                    fma2(acc[t][bp][0], x.y, we0);
                    fma2(acc[t][bp][1], x.y, we1);
                    fma2(acc[t][bp][2], x.y, we2);
                    fma2(acc[t][bp][3], x.y, we3);
                }
            }
        }
    }
}

// recurrent-phase: one 4-row group from smem weights against bp-packed h
__device__ __forceinline__ void phaseB_group(
    const float* __restrict__ Wsm, const float* __restrict__ hvec,
    int g, int lane, ull acc[NBP][4])
{
    const float4* wrow = (const float4*)(Wsm + g * 512) + lane;
#pragma unroll
    for (int half = 0; half < 2; half++) {
        float4 wa = wrow[half * 64];
        float4 wb = wrow[half * 64 + 32];
        ull wd0 = pk2(wa.x), wd1 = pk2(wa.y), wd2 = pk2(wa.z), wd3 = pk2(wa.w);
        ull we0 = pk2(wb.x), we1 = pk2(wb.y), we2 = pk2(wb.z), we3 = pk2(wb.w);
#pragma unroll
        for (int bp = 0; bp < NBP; bp++) {
            ulonglong2 h = *(const ulonglong2*)(hvec + bp * 64 + g * 8 + half * 4);
            fma2(acc[bp][0], h.x, wd0);
            fma2(acc[bp][1], h.x, wd1);
            fma2(acc[bp][2], h.x, wd2);
            fma2(acc[bp][3], h.x, wd3);
            fma2(acc[bp][0], h.y, we0);
            fma2(acc[bp][1], h.y, we1);
            fma2(acc[bp][2], h.y, we2);
            fma2(acc[bp][3], h.y, we3);
        }
    }
}

__global__ __launch_bounds__(NT, 2) void reslstm_kernel(
    const float* __restrict__ data,
    const float* __restrict__ w_hh0,
    const float* __restrict__ b_ih0, const float* __restrict__ b_hh0,
    const float* __restrict__ g0,    const float* __restrict__ be0,
    const float* __restrict__ w_hh1,
    const float* __restrict__ b_ih1, const float* __restrict__ b_hh1,
    const float* __restrict__ g1,    const float* __restrict__ be1,
    const float* __restrict__ dw,    const float* __restrict__ db,
    float* __restrict__ out)
{
    extern __shared__ float sm[];
    float* sWH0 = sm + OFF_WH0;
    float* sW1R = sm + OFF_W1R;
    float* sB0  = sm + OFF_B0;
    float* sB1  = sm + OFF_B1;
    float* sG0  = sm + OFF_G0;
    float* sBe0 = sm + OFF_BE0;
    float* sG1  = sm + OFF_G1;
    float* sBe1 = sm + OFF_BE1;
    float* sDW  = sm + OFF_DW;
    float* sDB  = sm + OFF_DB;

    const int tid  = threadIdx.x;
    const int lane = tid & 31;
    const int wid  = tid >> 5;

    // stage recurrent weights transposed+interleaved [k][j*4+g]
    for (int i = tid; i < 32 * 128; i += NT) {
        int k = i >> 7, rem = i & 127, j = rem >> 2, g = rem & 3;
        sWH0[i] = w_hh0[(g * 32 + j) * 32 + k];
        sW1R[i] = w_hh1[(g * 32 + j) * 32 + k];
    }
    for (int i = tid; i < 128; i += NT) {
        int j = i >> 2, g = i & 3;
        sB0[i] = b_ih0[g * 32 + j] + b_hh0[g * 32 + j];
        sB1[i] = b_ih1[g * 32 + j] + b_hh1[g * 32 + j];
    }
    for (int i = tid; i < 160; i += NT) {
        sG0[i] = g0[i]; sBe0[i] = be0[i];
        sG1[i] = g1[i]; sBe1[i] = be1[i];
    }
    for (int i = tid; i < 480; i += NT) sDW[i] = dw[i];
    if (tid < 3) sDB[tid] = db[tid];

    float* scrX  = sm + OFF_SCR + wid * SCR_W;  // [t*384 + bp*128 + n*2 + b]
    float* scrH  = scrX + 1920;                 // [bp*64 + k*2 + b]
    float* scrO0 = scrH + 192;                  // [t*192 + bp*64 + j*2 + b]
    float* scrO1 = scrX;                        // reuses X after L0 phase A

    const long long base = ((long long)blockIdx.x * NWARP + wid) * NB;

    // stage X (bp-packed; invalid batches and n=62,63 -> 0); init h=0
#pragma unroll
    for (int bi = 0; bi < NB; bi++) {
        int bp = bi >> 1, b = bi & 1;
        bool valid = (base + bi) < B_TOTAL;
        const float* dp = data + (base + bi) * (NF * TT);
        float* xw = scrX + bp * 128 + b;
#pragma unroll
        for (int t = 0; t < TT; t++) {
            xw[t * 384 + lane * 2] = valid ? __ldg(dp + lane * TT + t) : 0.0f;
            float xv = (valid && lane < NF - 32)
                           ? __ldg(dp + (lane + 32) * TT + t) : 0.0f;
            xw[t * 384 + (lane + 32) * 2] = xv;
        }
    }
#pragma unroll
    for (int i = 0; i < 6; i++) scrH[i * 32 + lane] = 0.0f;
    __syncthreads();

    const unsigned FULL = 0xffffffffu;

    // ======== layer 0: input phase (hoisted over t) ========
    ull acc[TT][NBP][4];
    {
        float4 b0q = *(const float4*)(sB0 + lane * 4);
        ull bd0 = pk2(b0q.x), bd1 = pk2(b0q.y), bd2 = pk2(b0q.z), bd3 = pk2(b0q.w);
#pragma unroll
        for (int t = 0; t < TT; t++)
#pragma unroll
            for (int bp = 0; bp < NBP; bp++) {
                acc[t][bp][0] = bd0; acc[t][bp][1] = bd1;
                acc[t][bp][2] = bd2; acc[t][bp][3] = bd3;
            }
    }
    phaseA(g_WI0T, scrX, 384, 128, 16, lane, acc);

    // ======== layer 0: recurrent phase ========
    float c0[NB];
#pragma unroll
    for (int bi = 0; bi < NB; bi++) c0[bi] = 0.f;

#pragma unroll
    for (int t = 0; t < TT; t++) {
#pragma unroll 1
        for (int g = 0; g < 8; g++)
            phaseB_group(sWH0, scrH, g, lane, acc[t]);
#pragma unroll
        for (int bp = 0; bp < NBP; bp++) {
            float i0, i1, f0, f1, gv0, gv1, ov0, ov1;
            unpk(acc[t][bp][0], i0, i1);
            unpk(acc[t][bp][1], f0, f1);
            unpk(acc[t][bp][2], gv0, gv1);
            unpk(acc[t][bp][3], ov0, ov1);
            float hb0, hb1;
            {
                int bi = bp * 2;
                float ig = sigm(i0), fg = sigm(f0), gg = tanh_f(gv0), og = sigm(ov0);
                c0[bi] = fg * c0[bi] + ig * gg;
                hb0 = og * tanh_f(c0[bi]);
            }
            {
                int bi = bp * 2 + 1;
                float ig = sigm(i1), fg = sigm(f1), gg = tanh_f(gv1), og = sigm(ov1);
                c0[bi] = fg * c0[bi] + ig * gg;
                hb1 = og * tanh_f(c0[bi]);
            }
            float2 hp = make_float2(hb0, hb1);
            *(float2*)(scrH + bp * 64 + lane * 2) = hp;
            *(float2*)(scrO0 + t * 192 + bp * 64 + lane * 2) = hp;
        }
        __syncwarp();
    }

    // ---- LN0 + LeakyReLU (in place in scrO0) ----
#pragma unroll
    for (int bi = 0; bi < NB; bi++) {
        int bp = bi >> 1, b = bi & 1;
        float v[TT];
        float s = 0.f, sq = 0.f;
#pragma unroll
        for (int t = 0; t < TT; t++) {
            v[t] = scrO0[t * 192 + bp * 64 + lane * 2 + b];
            s += v[t]; sq += v[t] * v[t];
        }
#pragma unroll
        for (int off = 16; off > 0; off >>= 1) {
            s  += __shfl_xor_sync(FULL, s,  off);
            sq += __shfl_xor_sync(FULL, sq, off);
        }
        float mu  = s * (1.0f / 160.0f);
        float var = sq * (1.0f / 160.0f) - mu * mu;
        float rs  = rsqrtf(var + 1e-5f);
#pragma unroll
        for (int t = 0; t < TT; t++) {
            float y = (v[t] - mu) * rs * sG0[t * 32 + lane] + sBe0[t * 32 + lane];
            scrO0[t * 192 + bp * 64 + lane * 2 + b] = lrelu(y);
        }
    }
#pragma unroll
    for (int i = 0; i < 6; i++) scrH[i * 32 + lane] = 0.0f;   // reset h for L1
    __syncwarp();

    // ======== layer 1: input phase over post-LN o0 ========
    {
        float4 b1q = *(const float4*)(sB1 + lane * 4);
        ull bd0 = pk2(b1q.x), bd1 = pk2(b1q.y), bd2 = pk2(b1q.z), bd3 = pk2(b1q.w);
#pragma unroll
        for (int t = 0; t < TT; t++)
#pragma unroll
            for (int bp = 0; bp < NBP; bp++) {
                acc[t][bp][0] = bd0; acc[t][bp][1] = bd1;
                acc[t][bp][2] = bd2; acc[t][bp][3] = bd3;
            }
    }
    phaseA(g_WI1T, scrO0, 192, 64, 8, lane, acc);

    // ======== layer 1: recurrent phase ========
    float c1[NB];
#pragma unroll
    for (int bi = 0; bi < NB; bi++) c1[bi] = 0.f;

#pragma unroll
    for (int t = 0; t < TT; t++) {
#pragma unroll 1
        for (int g = 0; g < 8; g++)
            phaseB_group(sW1R, scrH, g, lane, acc[t]);
#pragma unroll
        for (int bp = 0; bp < NBP; bp++) {
            float i0, i1, f0, f1, gv0, gv1, ov0, ov1;
            unpk(acc[t][bp][0], i0, i1);
            unpk(acc[t][bp][1], f0, f1);
            unpk(acc[t][bp][2], gv0, gv1);
            unpk(acc[t][bp][3], ov0, ov1);
            float hb0, hb1;
            {
                int bi = bp * 2;
                float ig = sigm(i0), fg = sigm(f0), gg = tanh_f(gv0), og = sigm(ov0);
                c1[bi] = fg * c1[bi] + ig * gg;
                hb0 = og * tanh_f(c1[bi]);
            }
            {
                int bi = bp * 2 + 1;
                float ig = sigm(i1), fg = sigm(f1), gg = tanh_f(gv1), og = sigm(ov1);
                c1[bi] = fg * c1[bi] + ig * gg;
                hb1 = og * tanh_f(c1[bi]);
            }
            float2 hp = make_float2(hb0, hb1);
            *(float2*)(scrH + bp * 64 + lane * 2) = hp;
            *(float2*)(scrO1 + t * 192 + bp * 64 + lane * 2) = hp;
        }
        __syncwarp();
    }

    // ---- LN1 + LeakyReLU + residual + head ----
#pragma unroll
    for (int bi = 0; bi < NB; bi++) {
        int bp = bi >> 1, b = bi & 1;
        float v[TT];
        float s = 0.f, sq = 0.f;
#pragma unroll
        for (int t = 0; t < TT; t++) {
            v[t] = scrO1[t * 192 + bp * 64 + lane * 2 + b];
            s += v[t]; sq += v[t] * v[t];
        }
#pragma unroll
        for (int off = 16; off > 0; off >>= 1) {
            s  += __shfl_xor_sync(FULL, s,  off);
            sq += __shfl_xor_sync(FULL, sq, off);
        }
        float mu  = s * (1.0f / 160.0f);
        float var = sq * (1.0f / 160.0f) - mu * mu;
        float rs  = rsqrtf(var + 1e-5f);

        float p0 = 0.f, p1 = 0.f, p2 = 0.f;
#pragma unroll
        for (int t = 0; t < TT; t++) {
            int idx = t * 32 + lane;
            float y = (v[t] - mu) * rs * sG1[idx] + sBe1[idx];
            float o = lrelu(y) + scrO0[t * 192 + bp * 64 + lane * 2 + b];
            p0 += o * sDW[idx];
            p1 += o * sDW[160 + idx];
            p2 += o * sDW[320 + idx];
        }
#pragma unroll
        for (int off = 16; off > 0; off >>= 1) {
            p0 += __shfl_xor_sync(FULL, p0, off);
            p1 += __shfl_xor_sync(FULL, p1, off);
            p2 += __shfl_xor_sync(FULL, p2, off);
        }
        if ((base + bi) < B_TOTAL && lane < 3) {
            float pv = (lane == 0) ? p0 : ((lane == 1) ? p1 : p2);
            pv += sDB[lane];
            out[(base + bi) * 3 + lane] = lrelu(pv);
        }
    }
}

extern "C" void kernel_launch(void* const* d_in, const int* in_sizes, int n_in,
                              void* d_out, int out_size) {
    const float* data  = (const float*)d_in[0];
    const float* w_ih0 = (const float*)d_in[1];
    const float* w_hh0 = (const float*)d_in[2];
    const float* b_ih0 = (const float*)d_in[3];
    const float* b_hh0 = (const float*)d_in[4];
    const float* g0    = (const float*)d_in[5];
    const float* be0   = (const float*)d_in[6];
    const float* w_ih1 = (const float*)d_in[7];
    const float* w_hh1 = (const float*)d_in[8];
    const float* b_ih1 = (const float*)d_in[9];
    const float* b_hh1 = (const float*)d_in[10];
    const float* g1    = (const float*)d_in[11];
    const float* be1   = (const float*)d_in[12];
    const float* dw    = (const float*)d_in[13];
    const float* db    = (const float*)d_in[14];
    float* out = (float*)d_out;

    cudaFuncSetAttribute(reslstm_kernel,
                         cudaFuncAttributeMaxDynamicSharedMemorySize, SMEM_BYTES);

    prep_kernel<<<12, 256>>>(w_ih0, w_ih1);

    int batches_per_cta = NWARP * NB;                       // 36
    int grid = (B_TOTAL + batches_per_cta - 1) / batches_per_cta;  // 3641
    reslstm_kernel<<<grid, NT, SMEM_BYTES>>>(
        data, w_hh0, b_ih0, b_hh0, g0, be0,
        w_hh1, b_ih1, b_hh1, g1, be1, dw, db, out);
}

// round 11
// speedup vs baseline: 2.0388x; 1.8568x over previous
#include <cuda_runtime.h>
#include <cuda_fp16.h>
#include <cstdint>

// ResLSTM on GB300, round 11: HMMA (mma.sync m16n8k16 f16/f32) rewrite.
// tcgen05 is unusable (harness PTX targets compute_103 without 'a').
// CTA = 128 batches, 8 warps; warp = 16 batch rows x 128 gate cols.
// Gate layout col = g*32+u makes the LSTM cell lane-local (no shuffles);
// h feeds back through warp-private fp16 smem tiles (no block syncs in
// the recurrence). LN/residual/head are per-thread (thread = batch).

#define MB       128
#define NT       256
#define TT       5
#define NF       62
#define B_TOTAL  131072
#define TILE_B   16384     // [128 rows][64 half] = 128B rows

#define OFF_X     0                      // 5 tiles: x -> o0 -> x1 -> o1
#define OFF_H     (5 * TILE_B)
#define OFF_WI0   (OFF_H + TILE_B)
#define OFF_WH0   (OFF_WI0 + TILE_B)
#define OFF_WI1   (OFF_WH0 + TILE_B)
#define OFF_WH1   (OFF_WI1 + TILE_B)
#define OFF_BIAS0 (OFF_WH1 + TILE_B)     // 128 f32
#define OFF_BIAS1 (OFF_BIAS0 + 512)
#define OFF_G0    (OFF_BIAS1 + 512)      // 160 f32
#define OFF_BE0   (OFF_G0 + 640)
#define OFF_G1    (OFF_BE0 + 640)
#define OFF_BE1   (OFF_G1 + 640)
#define OFF_DW    (OFF_BE1 + 640)        // 480 f32
#define OFF_DB    (OFF_DW + 1920)
#define SMEM_TOTAL (OFF_DB + 16)

#define SWZ(x) ((x) ^ (((x) >> 3) & 0x70))

__device__ __forceinline__ uint32_t smem_u32(const void* p) {
    uint32_t a;
    asm("{ .reg .u64 t; cvta.to.shared.u64 t, %1; cvt.u32.u64 %0, t; }"
        : "=r"(a) : "l"(p));
    return a;
}
__device__ __forceinline__ float tanh_f(float x) {
    float y; asm("tanh.approx.f32 %0, %1;" : "=f"(y) : "f"(x)); return y;
}
__device__ __forceinline__ float sigm(float x) {
    return fmaf(0.5f, tanh_f(0.5f * x), 0.5f);
}
__device__ __forceinline__ float lrelu(float x) {
    return x > 0.0f ? x : 0.01f * x;
}
__device__ __forceinline__ void ldmA(uint32_t a, uint32_t& r0, uint32_t& r1,
                                     uint32_t& r2, uint32_t& r3) {
    asm volatile("ldmatrix.sync.aligned.m8n8.x4.shared.b16 {%0,%1,%2,%3}, [%4];"
                 : "=r"(r0), "=r"(r1), "=r"(r2), "=r"(r3) : "r"(a));
}
__device__ __forceinline__ void ldmB(uint32_t a, uint32_t& r0, uint32_t& r1) {
    asm volatile("ldmatrix.sync.aligned.m8n8.x2.shared.b16 {%0,%1}, [%2];"
                 : "=r"(r0), "=r"(r1) : "r"(a));
}
__device__ __forceinline__ void mma16816(float* c, uint32_t a0, uint32_t a1,
                                         uint32_t a2, uint32_t a3,
                                         uint32_t b0, uint32_t b1) {
    asm volatile(
        "mma.sync.aligned.m16n8k16.row.col.f32.f16.f16.f32 "
        "{%0,%1,%2,%3}, {%4,%5,%6,%7}, {%8,%9}, {%0,%1,%2,%3};"
        : "+f"(c[0]), "+f"(c[1]), "+f"(c[2]), "+f"(c[3])
        : "r"(a0), "r"(a1), "r"(a2), "r"(a3), "r"(b0), "r"(b1));
}

template <int KC>
__device__ __forceinline__ void gemm_phase(
    uint32_t Atile, uint32_t Btile,
    uint32_t aoffbase, uint32_t boffrow, float (&acc)[16][4])
{
#pragma unroll
    for (int kc = 0; kc < KC; kc++) {
        uint32_t a0, a1, a2, a3;
        ldmA(Atile + SWZ(aoffbase + kc * 32), a0, a1, a2, a3);
#pragma unroll
        for (int nt = 0; nt < 16; nt++) {
            uint32_t b0, b1;
            ldmB(Btile + SWZ(boffrow + kc * 32) + nt * 1024, b0, b1);
            mma16816(acc[nt], a0, a1, a2, a3, b0, b1);
        }
    }
}

// LSTM cell epilogue: lane-local gates -> c,h; h -> H tile + X[t] tile (fp16)
__device__ __forceinline__ void lstm_epi(
    char* smem, int xoff, int warpRow, int l,
    float (&acc)[16][4], float (&cst)[16])
{
#pragma unroll
    for (int rh = 0; rh < 2; rh++) {
        int row = warpRow + (l >> 2) + rh * 8;
#pragma unroll
        for (int j = 0; j < 4; j++) {
            float hv0, hv1;
            {
                float ai = acc[j][rh * 2],      af = acc[4 + j][rh * 2];
                float ag = acc[8 + j][rh * 2],  ao = acc[12 + j][rh * 2];
                float cc = cst[rh * 8 + j * 2];
                cc = sigm(af) * cc + sigm(ai) * tanh_f(ag);
                cst[rh * 8 + j * 2] = cc;
                hv0 = sigm(ao) * tanh_f(cc);
            }
            {
                float ai = acc[j][rh * 2 + 1],     af = acc[4 + j][rh * 2 + 1];
                float ag = acc[8 + j][rh * 2 + 1], ao = acc[12 + j][rh * 2 + 1];
                float cc = cst[rh * 8 + j * 2 + 1];
                cc = sigm(af) * cc + sigm(ai) * tanh_f(ag);
                cst[rh * 8 + j * 2 + 1] = cc;
                hv1 = sigm(ao) * tanh_f(cc);
            }
            __half2 hp = __floats2half2_rn(hv0, hv1);
            uint32_t off = SWZ((uint32_t)(row * 128 + ((l & 3) * 2 + 8 * j) * 2));
            *(__half2*)(smem + OFF_H + off) = hp;
            *(__half2*)(smem + xoff + off) = hp;
        }
    }
}

__global__ __launch_bounds__(NT, 1) void reslstm_mma(
    const float* __restrict__ data,
    const float* __restrict__ w_ih0, const float* __restrict__ w_hh0,
    const float* __restrict__ b_ih0, const float* __restrict__ b_hh0,
    const float* __restrict__ g0,    const float* __restrict__ be0,
    const float* __restrict__ w_ih1, const float* __restrict__ w_hh1,
    const float* __restrict__ b_ih1, const float* __restrict__ b_hh1,
    const float* __restrict__ g1,    const float* __restrict__ be1,
    const float* __restrict__ dw,    const float* __restrict__ db,
    float* __restrict__ out)
{
    extern __shared__ char smem[];
    const uint32_t sb = smem_u32(smem);
    const int tid = threadIdx.x;
    const int l   = tid & 31;
    const int w   = tid >> 5;
    const int warpRow = w * 16;
    const long long gbase = (long long)blockIdx.x * MB;

    // ---- staging ----
    for (int i = tid; i < TILE_B / 16; i += NT)
        ((uint4*)(smem + OFF_H))[i] = make_uint4(0, 0, 0, 0);

    for (int i = tid; i < MB * NF * TT; i += NT) {
        int m = i / (NF * TT);
        int rem = i - m * (NF * TT);
        int n = rem / TT;
        int t = rem - n * TT;
        float v = data[((gbase + m) * NF + n) * TT + t];
        *(__half*)(smem + OFF_X + t * TILE_B + SWZ((uint32_t)(m * 128 + n * 2)))
            = __float2half(v);
    }
    for (int i = tid; i < MB * TT; i += NT) {   // pad n = 62,63
        int m = i / TT, t = i - m * TT;
        *(uint32_t*)(smem + OFF_X + t * TILE_B + SWZ((uint32_t)(m * 128 + 124))) = 0u;
    }
    for (int i = tid; i < 128 * 64; i += NT) {  // weights [n=col][k], fp16
        int r = i >> 6, k = i & 63;
        uint32_t so = SWZ((uint32_t)(r * 128 + k * 2));
        *(__half*)(smem + OFF_WI0 + so) = __float2half(k < NF ? w_ih0[r * NF + k] : 0.f);
        *(__half*)(smem + OFF_WH0 + so) = __float2half(k < 32 ? w_hh0[r * 32 + k] : 0.f);
        *(__half*)(smem + OFF_WI1 + so) = __float2half(k < 32 ? w_ih1[r * 32 + k] : 0.f);
        *(__half*)(smem + OFF_WH1 + so) = __float2half(k < 32 ? w_hh1[r * 32 + k] : 0.f);
    }
    if (tid < 128) {
        ((float*)(smem + OFF_BIAS0))[tid] = b_ih0[tid] + b_hh0[tid];
        ((float*)(smem + OFF_BIAS1))[tid] = b_ih1[tid] + b_hh1[tid];
    }
    for (int i = tid; i < 160; i += NT) {
        ((float*)(smem + OFF_G0))[i]  = g0[i];
        ((float*)(smem + OFF_BE0))[i] = be0[i];
        ((float*)(smem + OFF_G1))[i]  = g1[i];
        ((float*)(smem + OFF_BE1))[i] = be1[i];
    }
    for (int i = tid; i < 480; i += NT) ((float*)(smem + OFF_DW))[i] = dw[i];
    if (tid < 3) ((float*)(smem + OFF_DB))[tid] = db[tid];
    __syncthreads();

    // lane-constant fragment address bases (swizzle folded in per use)
    const uint32_t aoffbase = (uint32_t)((warpRow + (l & 15)) * 128 + ((l >> 4) << 4));
    const uint32_t boffrow  = (uint32_t)((l & 7) * 128 + (((l >> 3) & 1) << 4));

    float2 biasr[16];
#pragma unroll
    for (int nt = 0; nt < 16; nt++)
        biasr[nt] = *(const float2*)(smem + OFF_BIAS0 + (nt * 8 + (l & 3) * 2) * 4);

    float cst[16];
#pragma unroll
    for (int i = 0; i < 16; i++) cst[i] = 0.f;

    // ================= layer 0 =================
#pragma unroll 1
    for (int t = 0; t < TT; t++) {
        float acc[16][4];
#pragma unroll
        for (int nt = 0; nt < 16; nt++) {
            acc[nt][0] = biasr[nt].x; acc[nt][1] = biasr[nt].y;
            acc[nt][2] = biasr[nt].x; acc[nt][3] = biasr[nt].y;
        }
        gemm_phase<4>(sb + OFF_X + t * TILE_B, sb + OFF_WI0, aoffbase, boffrow, acc);
        gemm_phase<2>(sb + OFF_H, sb + OFF_WH0, aoffbase, boffrow, acc);
        lstm_epi(smem, OFF_X + t * TILE_B, warpRow, l, acc, cst);
        __syncwarp();
    }
    __syncthreads();

    // ---- LN0 + LeakyReLU + residual-part of head; write x1 (fp16) ----
    float p0 = 0.f, p1 = 0.f, p2 = 0.f;
    if (tid < 128) {
        int b = tid;
        float s = 0.f, sq = 0.f;
#pragma unroll
        for (int t = 0; t < TT; t++)
#pragma unroll
            for (int u2 = 0; u2 < 16; u2++) {
                uint32_t hv = *(uint32_t*)(smem + OFF_X + t * TILE_B
                                           + SWZ((uint32_t)(b * 128 + u2 * 4)));
                float2 v = __half22float2(*(__half2*)&hv);
                s += v.x + v.y; sq += v.x * v.x + v.y * v.y;
            }
        float mu  = s * (1.f / 160.f);
        float var = sq * (1.f / 160.f) - mu * mu;
        float rs  = rsqrtf(var + 1e-5f);
#pragma unroll
        for (int t = 0; t < TT; t++)
#pragma unroll
            for (int u2 = 0; u2 < 16; u2++) {
                uint32_t off = SWZ((uint32_t)(b * 128 + u2 * 4));
                uint32_t hv = *(uint32_t*)(smem + OFF_X + t * TILE_B + off);
                float2 v = __half22float2(*(__half2*)&hv);
                int idx = t * 32 + u2 * 2;
                float2 gg = *(const float2*)(smem + OFF_G0 + idx * 4);
                float2 bb = *(const float2*)(smem + OFF_BE0 + idx * 4);
                float y0 = lrelu((v.x - mu) * rs * gg.x + bb.x);
                float y1 = lrelu((v.y - mu) * rs * gg.y + bb.y);
                float2 d0 = *(const float2*)(smem + OFF_DW + idx * 4);
                float2 d1 = *(const float2*)(smem + OFF_DW + (160 + idx) * 4);
                float2 d2 = *(const float2*)(smem + OFF_DW + (320 + idx) * 4);
                p0 += y0 * d0.x + y1 * d0.y;
                p1 += y0 * d1.x + y1 * d1.y;
                p2 += y0 * d2.x + y1 * d2.y;
                *(__half2*)(smem + OFF_X + t * TILE_B + off) = __floats2half2_rn(y0, y1);
            }
    }
    __syncthreads();
    for (int i = tid; i < TILE_B / 16; i += NT)   // re-zero H for layer 1
        ((uint4*)(smem + OFF_H))[i] = make_uint4(0, 0, 0, 0);
    __syncthreads();

    // ================= layer 1 =================
#pragma unroll
    for (int nt = 0; nt < 16; nt++)
        biasr[nt] = *(const float2*)(smem + OFF_BIAS1 + (nt * 8 + (l & 3) * 2) * 4);
#pragma unroll
    for (int i = 0; i < 16; i++) cst[i] = 0.f;

#pragma unroll 1
    for (int t = 0; t < TT; t++) {
        float acc[16][4];
#pragma unroll
        for (int nt = 0; nt < 16; nt++) {
            acc[nt][0] = biasr[nt].x; acc[nt][1] = biasr[nt].y;
            acc[nt][2] = biasr[nt].x; acc[nt][3] = biasr[nt].y;
        }
        gemm_phase<2>(sb + OFF_X + t * TILE_B, sb + OFF_WI1, aoffbase, boffrow, acc);
        gemm_phase<2>(sb + OFF_H, sb + OFF_WH1, aoffbase, boffrow, acc);
        lstm_epi(smem, OFF_X + t * TILE_B, warpRow, l, acc, cst);
        __syncwarp();
    }
    __syncthreads();

    // ---- LN1 + LeakyReLU + head (residual already folded via LN0 pass) ----
    if (tid < 128) {
        int b = tid;
        float s = 0.f, sq = 0.f;
#pragma unroll
        for (int t = 0; t < TT; t++)
#pragma unroll
            for (int u2 = 0; u2 < 16; u2++) {
                uint32_t hv = *(uint32_t*)(smem + OFF_X + t * TILE_B
                                           + SWZ((uint32_t)(b * 128 + u2 * 4)));
                float2 v = __half22float2(*(__half2*)&hv);
                s += v.x + v.y; sq += v.x * v.x + v.y * v.y;
            }
        float mu  = s * (1.f / 160.f);
        float var = sq * (1.f / 160.f) - mu * mu;
        float rs  = rsqrtf(var + 1e-5f);
#pragma unroll
        for (int t = 0; t < TT; t++)
#pragma unroll
            for (int u2 = 0; u2 < 16; u2++) {
                uint32_t hv = *(uint32_t*)(smem + OFF_X + t * TILE_B
                                           + SWZ((uint32_t)(b * 128 + u2 * 4)));
                float2 v = __half22float2(*(__half2*)&hv);
                int idx = t * 32 + u2 * 2;
                float2 gg = *(const float2*)(smem + OFF_G1 + idx * 4);
                float2 bb = *(const float2*)(smem + OFF_BE1 + idx * 4);
                float y0 = lrelu((v.x - mu) * rs * gg.x + bb.x);
                float y1 = lrelu((v.y - mu) * rs * gg.y + bb.y);
                float2 d0 = *(const float2*)(smem + OFF_DW + idx * 4);
                float2 d1 = *(const float2*)(smem + OFF_DW + (160 + idx) * 4);
                float2 d2 = *(const float2*)(smem + OFF_DW + (320 + idx) * 4);
                p0 += y0 * d0.x + y1 * d0.y;
                p1 += y0 * d1.x + y1 * d1.y;
                p2 += y0 * d2.x + y1 * d2.y;
            }
        const float* sdb = (const float*)(smem + OFF_DB);
        long long ob = (gbase + b) * 3;
        out[ob + 0] = lrelu(p0 + sdb[0]);
        out[ob + 1] = lrelu(p1 + sdb[1]);
        out[ob + 2] = lrelu(p2 + sdb[2]);
    }
}

extern "C" void kernel_launch(void* const* d_in, const int* in_sizes, int n_in,
                              void* d_out, int out_size) {
    const float* data  = (const float*)d_in[0];
    const float* w_ih0 = (const float*)d_in[1];
    const float* w_hh0 = (const float*)d_in[2];
    const float* b_ih0 = (const float*)d_in[3];
    const float* b_hh0 = (const float*)d_in[4];
    const float* g0    = (const float*)d_in[5];
    const float* be0   = (const float*)d_in[6];
    const float* w_ih1 = (const float*)d_in[7];
    const float* w_hh1 = (const float*)d_in[8];
    const float* b_ih1 = (const float*)d_in[9];
    const float* b_hh1 = (const float*)d_in[10];
    const float* g1    = (const float*)d_in[11];
    const float* be1   = (const float*)d_in[12];
    const float* dw    = (const float*)d_in[13];
    const float* db    = (const float*)d_in[14];
    float* out = (float*)d_out;

    cudaFuncSetAttribute(reslstm_mma,
                         cudaFuncAttributeMaxDynamicSharedMemorySize, SMEM_TOTAL);

    int grid = B_TOTAL / MB;   // 1024
    reslstm_mma<<<grid, NT, SMEM_TOTAL>>>(
        data, w_ih0, w_hh0, b_ih0, b_hh0, g0, be0,
        w_ih1, w_hh1, b_ih1, b_hh1, g1, be1, dw, db, out);
}